// round 2
// baseline (speedup 1.0000x reference)
#include <cuda_runtime.h>
#include <math.h>

#define NB    32
#define LEN   4096
#define CH    128
#define NF    2048      // packed complex FFT size (LEN/2)
#define TOPK  64
#define NTHR  256
#define VPT   9         // 256*9 = 2304 >= 2049 bins
#define PADSZ 2308      // PADi(2047)=2302; also >= 2049 linear

// ---------------- device globals (scratch; no runtime allocation) ----------------
__device__ float  g_work[(size_t)NB * CH * LEN];   // 64 MB, (B,C,L)
__device__ float2 g_t2048[NF];                     // e^{-2pi i t / 2048}
__device__ float2 g_tsplit[NF];                    // e^{-pi i k / 2048}

// ---------------- twiddle init ----------------
__global__ void init_twiddles_k() {
    int i = blockIdx.x * blockDim.x + threadIdx.x;
    if (i < NF) {
        const double PI = 3.14159265358979323846;
        double a = -2.0 * PI * (double)i / (double)NF;
        g_t2048[i] = make_float2((float)cos(a), (float)sin(a));
        double b = -PI * (double)i / (double)NF;
        g_tsplit[i] = make_float2((float)cos(b), (float)sin(b));
    }
}

// ---------------- transposes ----------------
__global__ void transpose_in_k(const float* __restrict__ in) {
    __shared__ float tile[32][33];
    int b = blockIdx.z;
    int l0 = blockIdx.x << 5, c0 = blockIdx.y << 5;
    const float* p = in + (size_t)b * LEN * CH;
#pragma unroll
    for (int dy = 0; dy < 32; dy += 8)
        tile[threadIdx.y + dy][threadIdx.x] =
            p[(size_t)(l0 + threadIdx.y + dy) * CH + (c0 + threadIdx.x)];
    __syncthreads();
    float* q = g_work + (size_t)b * CH * LEN;
#pragma unroll
    for (int dy = 0; dy < 32; dy += 8)
        q[(size_t)(c0 + threadIdx.y + dy) * LEN + (l0 + threadIdx.x)] =
            tile[threadIdx.x][threadIdx.y + dy];
}

__global__ void transpose_out_k(float* __restrict__ out) {
    __shared__ float tile[32][33];
    int b = blockIdx.z;
    int l0 = blockIdx.x << 5, c0 = blockIdx.y << 5;
    const float* p = g_work + (size_t)b * CH * LEN;
#pragma unroll
    for (int dy = 0; dy < 32; dy += 8)
        tile[threadIdx.y + dy][threadIdx.x] =
            p[(size_t)(c0 + threadIdx.y + dy) * LEN + (l0 + threadIdx.x)];
    __syncthreads();
    float* q = out + (size_t)b * LEN * CH;
#pragma unroll
    for (int dy = 0; dy < 32; dy += 8)
        q[(size_t)(l0 + threadIdx.y + dy) * CH + (c0 + threadIdx.x)] =
            tile[threadIdx.x][threadIdx.y + dy];
}

// ---------------- complex helpers ----------------
__device__ __forceinline__ int PADi(int i) { return i + (i >> 3); }
__device__ __forceinline__ float2 cadd(float2 a, float2 b) { return make_float2(a.x + b.x, a.y + b.y); }
__device__ __forceinline__ float2 csub(float2 a, float2 b) { return make_float2(a.x - b.x, a.y - b.y); }
__device__ __forceinline__ float2 cmulf(float2 a, float2 b) {
    return make_float2(a.x * b.x - a.y * b.y, a.x * b.y + a.y * b.x);
}
__device__ __forceinline__ float2 mnegi(float2 a) { return make_float2(a.y, -a.x); } // a * (-i)

__device__ __forceinline__ void radix8(const float2* c, float2* d) {
    // E = DFT4(c0,c2,c4,c6), O = DFT4(c1,c3,c5,c7), X_k = E_k + W8^k O_k
    float2 s0 = cadd(c[0], c[4]), s1 = csub(c[0], c[4]);
    float2 s2 = cadd(c[2], c[6]), s3 = mnegi(csub(c[2], c[6]));
    float2 E0 = cadd(s0, s2), E2 = csub(s0, s2);
    float2 E1 = cadd(s1, s3), E3 = csub(s1, s3);
    float2 u0 = cadd(c[1], c[5]), u1 = csub(c[1], c[5]);
    float2 u2 = cadd(c[3], c[7]), u3 = mnegi(csub(c[3], c[7]));
    float2 O0 = cadd(u0, u2), O2 = csub(u0, u2);
    float2 O1 = cadd(u1, u3), O3 = csub(u1, u3);
    const float r2 = 0.70710678118654752f;
    float2 T1 = make_float2(r2 * (O1.x + O1.y), r2 * (O1.y - O1.x));   // W8^1*O1
    float2 T2 = mnegi(O2);                                             // W8^2*O2
    float2 T3 = make_float2(r2 * (O3.y - O3.x), r2 * (-O3.x - O3.y));  // W8^3*O3
    d[0] = cadd(E0, O0); d[4] = csub(E0, O0);
    d[1] = cadd(E1, T1); d[5] = csub(E1, T1);
    d[2] = cadd(E2, T2); d[6] = csub(E2, T2);
    d[3] = cadd(E3, T3); d[7] = csub(E3, T3);
}

// Stockham stage, radix 8. v[r]=src[j+r*256]; v[r]*=W_{8Ns}^{(j%Ns)*r}; DFT8;
// dst[(j/Ns)*8Ns + (j%Ns) + r*Ns] = v[r]
template <int Ns>
__device__ __forceinline__ void stage8(const float2* __restrict__ src,
                                       float2* __restrict__ dst, int j) {
    float2 v[8];
#pragma unroll
    for (int r = 0; r < 8; r++) v[r] = src[PADi(j + (r << 8))];
    if (Ns > 1) {
        const int step = NF / (Ns * 8);
        int tm = (j & (Ns - 1)) * step;
#pragma unroll
        for (int r = 1; r < 8; r++) v[r] = cmulf(v[r], g_t2048[tm * r]);
    }
    float2 d[8];
    radix8(v, d);
    int dbase = (j / Ns) * (Ns * 8) + (j & (Ns - 1));
#pragma unroll
    for (int r = 0; r < 8; r++) dst[PADi(dbase + r * Ns)] = d[r];
}

// final radix-4 stage (Ns=512), 2 butterflies per thread
__device__ __forceinline__ void stage4_last(const float2* __restrict__ src,
                                            float2* __restrict__ dst, int t) {
#pragma unroll
    for (int h = 0; h < 2; h++) {
        int j = t + (h << 8);   // 0..511
        float2 v0 = src[PADi(j)];
        float2 v1 = cmulf(src[PADi(j + 512)],  g_t2048[j]);
        float2 v2 = cmulf(src[PADi(j + 1024)], g_t2048[2 * j]);
        float2 v3 = cmulf(src[PADi(j + 1536)], g_t2048[3 * j]);
        float2 s0 = cadd(v0, v2), s1 = csub(v0, v2);
        float2 s2 = cadd(v1, v3), s3 = mnegi(csub(v1, v3));
        dst[PADi(j)]        = cadd(s0, s2);
        dst[PADi(j + 512)]  = cadd(s1, s3);
        dst[PADi(j + 1024)] = csub(s0, s2);
        dst[PADi(j + 1536)] = csub(s1, s3);
    }
}

// forward 2048-pt complex FFT: input PAD-mapped in A, result PAD-mapped in A, synced
__device__ __forceinline__ void fft2048(float2* A, float2* B, int t) {
    stage8<1>(A, B, t);   __syncthreads();
    stage8<8>(B, A, t);   __syncthreads();
    stage8<64>(A, B, t);  __syncthreads();
    stage4_last(B, A, t); __syncthreads();
}

// ---------------- main per-row kernel ----------------
__global__ void __launch_bounds__(NTHR, 2) fourier_rows_k() {
    __shared__ float2 bufA[PADSZ];
    __shared__ float2 bufB[PADSZ];
    __shared__ unsigned hist[256];
    __shared__ unsigned warpsum[8];
    __shared__ unsigned scal[2];

    int t = threadIdx.x;
    float* rp = g_work + (size_t)blockIdx.x * LEN;

    // load row as packed complex z[n] = x[2n] + i x[2n+1]
    for (int i = t; i < NF; i += NTHR)
        bufA[PADi(i)] = reinterpret_cast<const float2*>(rp)[i];
    __syncthreads();

    fft2048(bufA, bufB, t);   // Z in bufA (PAD)

    // split: X[k] = E + W_k * O, k=0..2048; X -> bufB (linear), keys = bits(|X|^2)
    unsigned keys[VPT];
#pragma unroll
    for (int v = 0; v < VPT; v++) {
        int k = t * VPT + v;
        if (k <= NF) {
            float2 Zk = bufA[PADi(k & (NF - 1))];
            float2 Zn = bufA[PADi((NF - k) & (NF - 1))];
            float2 E  = make_float2(0.5f * (Zk.x + Zn.x), 0.5f * (Zk.y - Zn.y));
            float2 D  = make_float2(Zk.x - Zn.x, Zk.y + Zn.y);
            float2 O  = make_float2(0.5f * D.y, -0.5f * D.x);   // D/(2i)
            float2 W  = (k < NF) ? g_tsplit[k] : make_float2(-1.f, 0.f);
            float2 X  = cadd(E, cmulf(O, W));
            bufB[k] = X;
            keys[v] = __float_as_uint(X.x * X.x + X.y * X.y);
        } else {
            keys[v] = 0u;
        }
    }
    __syncthreads();

    // radix-select the TOPK-th largest key: 4 passes of 8 bits, MSB first
    unsigned pref = 0u;
    int remain = TOPK;
#pragma unroll
    for (int shift = 24; shift >= 0; shift -= 8) {
        hist[t] = 0u;
        __syncthreads();
        unsigned himask = (shift == 24) ? 0u : (0xFFFFFFFFu << (shift + 8));
#pragma unroll
        for (int v = 0; v < VPT; v++) {
            unsigned key = keys[v];
            unsigned bucket = ((key & himask) == (pref & himask))
                                  ? ((key >> shift) & 255u) : 0xFFFFu;
            unsigned mm = __match_any_sync(0xFFFFFFFFu, bucket);
            if (bucket != 0xFFFFu && (t & 31) == (__ffs(mm) - 1))
                atomicAdd(&hist[bucket], (unsigned)__popc(mm));
        }
        __syncthreads();
        if (t < 32) {
            unsigned cnts[8]; unsigned lsum = 0;
#pragma unroll
            for (int e = 0; e < 8; e++) { cnts[e] = hist[255 - (t * 8 + e)]; lsum += cnts[e]; }
            unsigned inc = lsum;
#pragma unroll
            for (int o = 1; o < 32; o <<= 1) {
                unsigned nn = __shfl_up_sync(0xFFFFFFFFu, inc, o);
                if (t >= o) inc += nn;
            }
            int excl = (int)(inc - lsum);  // keys strictly above this lane's bucket range
            if (excl < remain && remain <= (int)inc) {
                int run = excl;
#pragma unroll
                for (int e = 0; e < 8; e++) {
                    if (run < remain && remain <= run + (int)cnts[e]) {
                        scal[0] = (unsigned)(255 - (t * 8 + e));
                        scal[1] = (unsigned)run;
                    }
                    run += (int)cnts[e];
                }
            }
        }
        __syncthreads();
        pref |= (scal[0] << shift);
        remain -= (int)scal[1];
        __syncthreads();
    }
    unsigned Tkey = pref;   // exact key of the TOPK-th largest
    int extra = remain;     // number of ties (== Tkey) to keep, lowest bin index first

    // per-thread exclusive rank among ties (global order = bin index order)
    int local = 0;
#pragma unroll
    for (int v = 0; v < VPT; v++) {
        int k = t * VPT + v;
        if (k <= NF && keys[v] == Tkey) local++;
    }
    int inc2 = local;
#pragma unroll
    for (int o = 1; o < 32; o <<= 1) {
        int nn = __shfl_up_sync(0xFFFFFFFFu, inc2, o);
        if ((t & 31) >= o) inc2 += nn;
    }
    if ((t & 31) == 31) warpsum[t >> 5] = (unsigned)inc2;
    __syncthreads();
    if (t == 0) {
        unsigned acc = 0;
        for (int w = 0; w < 8; w++) { unsigned s = warpsum[w]; warpsum[w] = acc; acc += s; }
    }
    __syncthreads();
    int rank = (int)warpsum[t >> 5] + (inc2 - local);

    // zero non-selected bins of X
#pragma unroll
    for (int v = 0; v < VPT; v++) {
        int k = t * VPT + v;
        if (k <= NF) {
            bool sel;
            if (keys[v] > Tkey) sel = true;
            else if (keys[v] == Tkey) { sel = (rank < extra); rank++; }
            else sel = false;
            if (!sel) bufB[k] = make_float2(0.f, 0.f);
        }
    }
    __syncthreads();

    // rebuild Z' from masked X; store conj(Z') for inverse via forward FFT
    for (int k = t; k < NF; k += NTHR) {
        float2 Xk = bufB[k];
        float2 Xn = bufB[NF - k];   // k=0 -> Nyquist bin 2048
        float2 E  = make_float2(0.5f * (Xk.x + Xn.x), 0.5f * (Xk.y - Xn.y));
        float2 Dh = make_float2(0.5f * (Xk.x - Xn.x), 0.5f * (Xk.y + Xn.y)); // = W^k O
        float2 W  = g_tsplit[k];
        float2 Wc = make_float2(W.x, -W.y);
        float2 O  = cmulf(Dh, Wc);
        // Z' = E + iO ; store conj(Z') = (E.x - O.y, -(E.y + O.x))
        bufA[PADi(k)] = make_float2(E.x - O.y, -(E.y + O.x));
    }
    __syncthreads();

    fft2048(bufA, bufB, t);       // F = FFT(conj(Z')) = NF * conj(z')

    const float invn = 1.0f / (float)NF;
    for (int i = t; i < NF; i += NTHR) {
        float2 r = bufA[PADi(i)];
        // z'[n] = conj(F[n])/NF : x'[2n] = F.x/NF, x'[2n+1] = -F.y/NF
        reinterpret_cast<float2*>(rp)[i] = make_float2(r.x * invn, -r.y * invn);
    }
}

// ---------------- launch ----------------
extern "C" void kernel_launch(void* const* d_in, const int* in_sizes, int n_in,
                              void* d_out, int out_size) {
    const float* x = (const float*)d_in[0];
    float* out = (float*)d_out;

    init_twiddles_k<<<(NF + 255) / 256, 256>>>();

    dim3 tb(32, 8);
    dim3 tg(LEN / 32, CH / 32, NB);
    transpose_in_k<<<tg, tb>>>(x);

    fourier_rows_k<<<NB * CH, NTHR>>>();

    transpose_out_k<<<tg, tb>>>(out);
}

// round 3
// speedup vs baseline: 1.3216x; 1.3216x over previous
#include <cuda_runtime.h>
#include <math.h>

#define NB    32
#define LEN   4096
#define CH    128
#define NF    2048      // packed complex FFT size (LEN/2)
#define TOPK  64
#define NTHR  256
#define VPT   9         // 256*9 = 2304 >= 2049 bins
#define PADB  2308      // single in-place buffer; PADi(2048)=2304 is the Nyquist slot

// ---------------- device globals (scratch; no runtime allocation) ----------------
__device__ float  g_work[(size_t)NB * CH * LEN];   // 64 MB, (B,C,L)
__device__ float2 g_t2048[NF];                     // e^{-2pi i t / 2048}
__device__ float2 g_tsplit[NF];                    // e^{-pi i k / 2048}

// ---------------- twiddle init ----------------
__global__ void init_twiddles_k() {
    int i = blockIdx.x * blockDim.x + threadIdx.x;
    if (i < NF) {
        const double PI = 3.14159265358979323846;
        double a = -2.0 * PI * (double)i / (double)NF;
        g_t2048[i] = make_float2((float)cos(a), (float)sin(a));
        double b = -PI * (double)i / (double)NF;
        g_tsplit[i] = make_float2((float)cos(b), (float)sin(b));
    }
}

// ---------------- transposes ----------------
__global__ void transpose_in_k(const float* __restrict__ in) {
    __shared__ float tile[32][33];
    int b = blockIdx.z;
    int l0 = blockIdx.x << 5, c0 = blockIdx.y << 5;
    const float* p = in + (size_t)b * LEN * CH;
#pragma unroll
    for (int dy = 0; dy < 32; dy += 8)
        tile[threadIdx.y + dy][threadIdx.x] =
            p[(size_t)(l0 + threadIdx.y + dy) * CH + (c0 + threadIdx.x)];
    __syncthreads();
    float* q = g_work + (size_t)b * CH * LEN;
#pragma unroll
    for (int dy = 0; dy < 32; dy += 8)
        q[(size_t)(c0 + threadIdx.y + dy) * LEN + (l0 + threadIdx.x)] =
            tile[threadIdx.x][threadIdx.y + dy];
}

__global__ void transpose_out_k(float* __restrict__ out) {
    __shared__ float tile[32][33];
    int b = blockIdx.z;
    int l0 = blockIdx.x << 5, c0 = blockIdx.y << 5;
    const float* p = g_work + (size_t)b * CH * LEN;
#pragma unroll
    for (int dy = 0; dy < 32; dy += 8)
        tile[threadIdx.y + dy][threadIdx.x] =
            p[(size_t)(c0 + threadIdx.y + dy) * LEN + (l0 + threadIdx.x)];
    __syncthreads();
    float* q = out + (size_t)b * LEN * CH;
#pragma unroll
    for (int dy = 0; dy < 32; dy += 8)
        q[(size_t)(l0 + threadIdx.y + dy) * CH + (c0 + threadIdx.x)] =
            tile[threadIdx.x][threadIdx.y + dy];
}

// ---------------- complex helpers ----------------
__device__ __forceinline__ int PADi(int i) { return i + (i >> 3); }
__device__ __forceinline__ float2 cadd(float2 a, float2 b) { return make_float2(a.x + b.x, a.y + b.y); }
__device__ __forceinline__ float2 csub(float2 a, float2 b) { return make_float2(a.x - b.x, a.y - b.y); }
__device__ __forceinline__ float2 cmulf(float2 a, float2 b) {
    return make_float2(a.x * b.x - a.y * b.y, a.x * b.y + a.y * b.x);
}
__device__ __forceinline__ float2 mnegi(float2 a) { return make_float2(a.y, -a.x); } // a * (-i)

__device__ __forceinline__ void radix8(const float2* c, float2* d) {
    float2 s0 = cadd(c[0], c[4]), s1 = csub(c[0], c[4]);
    float2 s2 = cadd(c[2], c[6]), s3 = mnegi(csub(c[2], c[6]));
    float2 E0 = cadd(s0, s2), E2 = csub(s0, s2);
    float2 E1 = cadd(s1, s3), E3 = csub(s1, s3);
    float2 u0 = cadd(c[1], c[5]), u1 = csub(c[1], c[5]);
    float2 u2 = cadd(c[3], c[7]), u3 = mnegi(csub(c[3], c[7]));
    float2 O0 = cadd(u0, u2), O2 = csub(u0, u2);
    float2 O1 = cadd(u1, u3), O3 = csub(u1, u3);
    const float r2 = 0.70710678118654752f;
    float2 T1 = make_float2(r2 * (O1.x + O1.y), r2 * (O1.y - O1.x));   // W8^1*O1
    float2 T2 = mnegi(O2);                                             // W8^2*O2
    float2 T3 = make_float2(r2 * (O3.y - O3.x), r2 * (-O3.x - O3.y));  // W8^3*O3
    d[0] = cadd(E0, O0); d[4] = csub(E0, O0);
    d[1] = cadd(E1, T1); d[5] = csub(E1, T1);
    d[2] = cadd(E2, T2); d[6] = csub(E2, T2);
    d[3] = cadd(E3, T3); d[7] = csub(E3, T3);
}

// in-place Stockham stage, radix 8: read 8 -> regs, compute, barrier, write 8
template <int Ns>
__device__ __forceinline__ void stage8_ip(float2* __restrict__ buf, int j) {
    float2 v[8];
#pragma unroll
    for (int r = 0; r < 8; r++) v[r] = buf[PADi(j + (r << 8))];
    if (Ns > 1) {
        const int step = NF / (Ns * 8);
        int tm = (j & (Ns - 1)) * step;
#pragma unroll
        for (int r = 1; r < 8; r++) v[r] = cmulf(v[r], g_t2048[tm * r]);
    }
    float2 d[8];
    radix8(v, d);
    int dbase = (j / Ns) * (Ns * 8) + (j & (Ns - 1));
    __syncthreads();
#pragma unroll
    for (int r = 0; r < 8; r++) buf[PADi(dbase + r * Ns)] = d[r];
}

// final radix-4 stage (Ns=512): per-thread slots are read AND written by the
// same thread only -> fully in-place, no internal barrier needed.
__device__ __forceinline__ void stage4_ip(float2* __restrict__ buf, int t) {
#pragma unroll
    for (int h = 0; h < 2; h++) {
        int j = t + (h << 8);   // 0..511
        float2 v0 = buf[PADi(j)];
        float2 v1 = cmulf(buf[PADi(j + 512)],  g_t2048[j]);
        float2 v2 = cmulf(buf[PADi(j + 1024)], g_t2048[2 * j]);
        float2 v3 = cmulf(buf[PADi(j + 1536)], g_t2048[3 * j]);
        float2 s0 = cadd(v0, v2), s1 = csub(v0, v2);
        float2 s2 = cadd(v1, v3), s3 = mnegi(csub(v1, v3));
        buf[PADi(j)]        = cadd(s0, s2);
        buf[PADi(j + 512)]  = cadd(s1, s3);
        buf[PADi(j + 1024)] = csub(s0, s2);
        buf[PADi(j + 1536)] = csub(s1, s3);
    }
}

// forward 2048-pt complex FFT, in place, synced on exit
__device__ __forceinline__ void fft2048_ip(float2* buf, int t) {
    stage8_ip<1>(buf, t);   __syncthreads();
    stage8_ip<8>(buf, t);   __syncthreads();
    stage8_ip<64>(buf, t);  __syncthreads();
    stage4_ip(buf, t);      __syncthreads();
}

// ---------------- main per-row kernel ----------------
__global__ void __launch_bounds__(NTHR, 4) fourier_rows_k() {
    __shared__ float2 buf[PADB];
    __shared__ unsigned hist[256];
    __shared__ unsigned warpsum[8];
    __shared__ unsigned scal[2];

    int t = threadIdx.x;
    float* rp = g_work + (size_t)blockIdx.x * LEN;

    // load row as packed complex z[n] = x[2n] + i x[2n+1]
    for (int i = t; i < NF; i += NTHR)
        buf[PADi(i)] = reinterpret_cast<const float2*>(rp)[i];
    __syncthreads();

    fft2048_ip(buf, t);   // Z in buf

    // rfft split, in place, pairwise (k, 2048-k). Each pair's slots are read
    // and written by one thread -> race-free without a barrier.
    // X[k] = E + W_k*O from Z[k], Z[2048-k];   W_{2048-k} = (-W.x, W.y).
    for (int k = t; k <= NF / 2; k += NTHR) {
        float2 Zk = buf[PADi(k & (NF - 1))];
        float2 Zn = buf[PADi((NF - k) & (NF - 1))];
        float2 W  = g_tsplit[k];
        // X[k]
        float2 E  = make_float2(0.5f * (Zk.x + Zn.x), 0.5f * (Zk.y - Zn.y));
        float2 D  = make_float2(Zk.x - Zn.x, Zk.y + Zn.y);
        float2 O  = make_float2(0.5f * D.y, -0.5f * D.x);   // D/(2i)
        float2 Xk = cadd(E, cmulf(O, W));
        // X[2048-k] (swap roles, W'' = (-W.x, W.y))
        float2 E2 = make_float2(0.5f * (Zn.x + Zk.x), 0.5f * (Zn.y - Zk.y));
        float2 D2 = make_float2(Zn.x - Zk.x, Zn.y + Zk.y);
        float2 O2 = make_float2(0.5f * D2.y, -0.5f * D2.x);
        float2 W2 = make_float2(-W.x, W.y);
        float2 Xn = cadd(E2, cmulf(O2, W2));
        buf[PADi(k)] = Xk;
        buf[PADi(NF - k)] = Xn;     // k=0 -> Nyquist slot PADi(2048)=2304
    }
    __syncthreads();

    // keys = bits(|X|^2), thread t owns bins t*VPT..t*VPT+VPT-1
    unsigned keys[VPT];
#pragma unroll
    for (int v = 0; v < VPT; v++) {
        int k = t * VPT + v;
        if (k <= NF) {
            float2 X = buf[PADi(k)];
            keys[v] = __float_as_uint(X.x * X.x + X.y * X.y);
        } else {
            keys[v] = 0u;
        }
    }

    // radix-select the TOPK-th largest key: 4 passes of 8 bits, MSB first
    unsigned pref = 0u;
    int remain = TOPK;
#pragma unroll
    for (int shift = 24; shift >= 0; shift -= 8) {
        hist[t] = 0u;
        __syncthreads();
        unsigned himask = (shift == 24) ? 0u : (0xFFFFFFFFu << (shift + 8));
#pragma unroll
        for (int v = 0; v < VPT; v++) {
            unsigned key = keys[v];
            unsigned bucket = ((key & himask) == (pref & himask))
                                  ? ((key >> shift) & 255u) : 0xFFFFu;
            unsigned mm = __match_any_sync(0xFFFFFFFFu, bucket);
            if (bucket != 0xFFFFu && (t & 31) == (__ffs(mm) - 1))
                atomicAdd(&hist[bucket], (unsigned)__popc(mm));
        }
        __syncthreads();
        if (t < 32) {
            unsigned cnts[8]; unsigned lsum = 0;
#pragma unroll
            for (int e = 0; e < 8; e++) { cnts[e] = hist[255 - (t * 8 + e)]; lsum += cnts[e]; }
            unsigned inc = lsum;
#pragma unroll
            for (int o = 1; o < 32; o <<= 1) {
                unsigned nn = __shfl_up_sync(0xFFFFFFFFu, inc, o);
                if (t >= o) inc += nn;
            }
            int excl = (int)(inc - lsum);  // keys strictly above this lane's range
            if (excl < remain && remain <= (int)inc) {
                int run = excl;
#pragma unroll
                for (int e = 0; e < 8; e++) {
                    if (run < remain && remain <= run + (int)cnts[e]) {
                        scal[0] = (unsigned)(255 - (t * 8 + e));
                        scal[1] = (unsigned)run;
                    }
                    run += (int)cnts[e];
                }
            }
        }
        __syncthreads();
        pref |= (scal[0] << shift);
        remain -= (int)scal[1];
        __syncthreads();
    }
    unsigned Tkey = pref;   // exact key of the TOPK-th largest
    int extra = remain;     // ties (== Tkey) to keep, lowest bin index first

    // per-thread exclusive rank among ties (global order = bin index order)
    int local = 0;
#pragma unroll
    for (int v = 0; v < VPT; v++) {
        int k = t * VPT + v;
        if (k <= NF && keys[v] == Tkey) local++;
    }
    int inc2 = local;
#pragma unroll
    for (int o = 1; o < 32; o <<= 1) {
        int nn = __shfl_up_sync(0xFFFFFFFFu, inc2, o);
        if ((t & 31) >= o) inc2 += nn;
    }
    if ((t & 31) == 31) warpsum[t >> 5] = (unsigned)inc2;
    __syncthreads();
    if (t == 0) {
        unsigned acc = 0;
        for (int w = 0; w < 8; w++) { unsigned s = warpsum[w]; warpsum[w] = acc; acc += s; }
    }
    __syncthreads();
    int rank = (int)warpsum[t >> 5] + (inc2 - local);

    // zero non-selected bins of X (in place)
#pragma unroll
    for (int v = 0; v < VPT; v++) {
        int k = t * VPT + v;
        if (k <= NF) {
            bool sel;
            if (keys[v] > Tkey) sel = true;
            else if (keys[v] == Tkey) { sel = (rank < extra); rank++; }
            else sel = false;
            if (!sel) buf[PADi(k)] = make_float2(0.f, 0.f);
        }
    }
    __syncthreads();

    // rebuild conj(Z') from masked X, in place, pairwise.
    // Z'[k] = E + iO, O = (W^k O) * conj(W_k); store conj(Z').
    for (int k = t; k <= NF / 2; k += NTHR) {
        float2 Xk = buf[PADi(k)];
        float2 Xn = buf[PADi(NF - k)];   // k=0 -> Nyquist slot 2304
        float2 W  = g_tsplit[k];
        // Z'[k]
        float2 E  = make_float2(0.5f * (Xk.x + Xn.x), 0.5f * (Xk.y - Xn.y));
        float2 Dh = make_float2(0.5f * (Xk.x - Xn.x), 0.5f * (Xk.y + Xn.y)); // W^k O
        float2 O  = cmulf(Dh, make_float2(W.x, -W.y));
        float2 zck = make_float2(E.x - O.y, -(E.y + O.x));   // conj(Z'[k])
        // Z'[2048-k], W'' = (-W.x, W.y), conj(W'') = (-W.x, -W.y)
        float2 E2  = make_float2(0.5f * (Xn.x + Xk.x), 0.5f * (Xn.y - Xk.y));
        float2 Dh2 = make_float2(0.5f * (Xn.x - Xk.x), 0.5f * (Xn.y + Xk.y));
        float2 O2  = cmulf(Dh2, make_float2(-W.x, -W.y));
        float2 zcn = make_float2(E2.x - O2.y, -(E2.y + O2.x));
        buf[PADi(k)] = zck;
        if (k > 0) buf[PADi(NF - k)] = zcn;   // slot 2048 not part of Z'
    }
    __syncthreads();

    fft2048_ip(buf, t);       // F = FFT(conj(Z')) = NF * conj(z')

    const float invn = 1.0f / (float)NF;
    for (int i = t; i < NF; i += NTHR) {
        float2 r = buf[PADi(i)];
        // z'[n] = conj(F[n])/NF : x'[2n] = F.x/NF, x'[2n+1] = -F.y/NF
        reinterpret_cast<float2*>(rp)[i] = make_float2(r.x * invn, -r.y * invn);
    }
}

// ---------------- launch ----------------
extern "C" void kernel_launch(void* const* d_in, const int* in_sizes, int n_in,
                              void* d_out, int out_size) {
    const float* x = (const float*)d_in[0];
    float* out = (float*)d_out;

    init_twiddles_k<<<(NF + 255) / 256, 256>>>();

    dim3 tb(32, 8);
    dim3 tg(LEN / 32, CH / 32, NB);
    transpose_in_k<<<tg, tb>>>(x);

    fourier_rows_k<<<NB * CH, NTHR>>>();

    transpose_out_k<<<tg, tb>>>(out);
}

// round 4
// speedup vs baseline: 1.3631x; 1.0314x over previous
#include <cuda_runtime.h>
#include <math.h>

#define NB    32
#define LEN   4096
#define CH    128
#define NF    2048      // packed complex FFT size (LEN/2)
#define TOPK  64
#define NTHR  128
#define VPT   17        // 128*17 = 2176 >= 2049 bins
#define PADB  2308      // PADi(2048)=2304 is the Nyquist slot

// ---------------- device globals (scratch; no runtime allocation) ----------------
__device__ float  g_work[(size_t)NB * CH * LEN];   // 64 MB, (B,C,L)
__device__ float2 g_t2048[NF];                     // e^{-2pi i t / 2048}
__device__ float2 g_tsplit[NF];                    // e^{-pi i k / 2048}

// ---------------- twiddle init ----------------
__global__ void init_twiddles_k() {
    int i = blockIdx.x * blockDim.x + threadIdx.x;
    if (i < NF) {
        const double PI = 3.14159265358979323846;
        double a = -2.0 * PI * (double)i / (double)NF;
        g_t2048[i] = make_float2((float)cos(a), (float)sin(a));
        double b = -PI * (double)i / (double)NF;
        g_tsplit[i] = make_float2((float)cos(b), (float)sin(b));
    }
}

// ---------------- transposes (float4 vectorized, blockDim (8,32)) ----------------
__global__ void transpose_in_k(const float* __restrict__ in) {
    __shared__ float tile[32][33];
    int b = blockIdx.z;
    int l0 = blockIdx.x << 5, c0 = blockIdx.y << 5;
    int x = threadIdx.x, y = threadIdx.y;
    float4 v = *reinterpret_cast<const float4*>(
        in + (size_t)b * LEN * CH + (size_t)(l0 + y) * CH + c0 + 4 * x);
    tile[y][4 * x + 0] = v.x; tile[y][4 * x + 1] = v.y;
    tile[y][4 * x + 2] = v.z; tile[y][4 * x + 3] = v.w;
    __syncthreads();
    float4 w;
    w.x = tile[4 * x + 0][y]; w.y = tile[4 * x + 1][y];
    w.z = tile[4 * x + 2][y]; w.w = tile[4 * x + 3][y];
    *reinterpret_cast<float4*>(
        g_work + (size_t)b * CH * LEN + (size_t)(c0 + y) * LEN + l0 + 4 * x) = w;
}

__global__ void transpose_out_k(float* __restrict__ out) {
    __shared__ float tile[32][33];
    int b = blockIdx.z;
    int l0 = blockIdx.x << 5, c0 = blockIdx.y << 5;
    int x = threadIdx.x, y = threadIdx.y;
    float4 v = *reinterpret_cast<const float4*>(
        g_work + (size_t)b * CH * LEN + (size_t)(c0 + y) * LEN + l0 + 4 * x);
    tile[4 * x + 0][y] = v.x; tile[4 * x + 1][y] = v.y;
    tile[4 * x + 2][y] = v.z; tile[4 * x + 3][y] = v.w;
    __syncthreads();
    float4 w;
    w.x = tile[y][4 * x + 0]; w.y = tile[y][4 * x + 1];
    w.z = tile[y][4 * x + 2]; w.w = tile[y][4 * x + 3];
    *reinterpret_cast<float4*>(
        out + (size_t)b * LEN * CH + (size_t)(l0 + y) * CH + c0 + 4 * x) = w;
}

// ---------------- complex helpers ----------------
__device__ __forceinline__ int PADi(int i) { return i + (i >> 3); }
__device__ __forceinline__ float2 cadd(float2 a, float2 b) { return make_float2(a.x + b.x, a.y + b.y); }
__device__ __forceinline__ float2 csub(float2 a, float2 b) { return make_float2(a.x - b.x, a.y - b.y); }
__device__ __forceinline__ float2 cmulf(float2 a, float2 b) {
    return make_float2(a.x * b.x - a.y * b.y, a.x * b.y + a.y * b.x);
}
__device__ __forceinline__ float2 mnegi(float2 a) { return make_float2(a.y, -a.x); } // a * (-i)
// a * (c - i s)
__device__ __forceinline__ float2 mulW(float2 a, float c, float s) {
    return make_float2(a.x * c + a.y * s, a.y * c - a.x * s);
}

__device__ __forceinline__ void radix8(const float2* c, float2* d) {
    float2 s0 = cadd(c[0], c[4]), s1 = csub(c[0], c[4]);
    float2 s2 = cadd(c[2], c[6]), s3 = mnegi(csub(c[2], c[6]));
    float2 E0 = cadd(s0, s2), E2 = csub(s0, s2);
    float2 E1 = cadd(s1, s3), E3 = csub(s1, s3);
    float2 u0 = cadd(c[1], c[5]), u1 = csub(c[1], c[5]);
    float2 u2 = cadd(c[3], c[7]), u3 = mnegi(csub(c[3], c[7]));
    float2 O0 = cadd(u0, u2), O2 = csub(u0, u2);
    float2 O1 = cadd(u1, u3), O3 = csub(u1, u3);
    const float r2 = 0.70710678118654752f;
    float2 T1 = make_float2(r2 * (O1.x + O1.y), r2 * (O1.y - O1.x));   // W8^1*O1
    float2 T2 = mnegi(O2);                                             // W8^2*O2
    float2 T3 = make_float2(r2 * (O3.y - O3.x), r2 * (-O3.x - O3.y));  // W8^3*O3
    d[0] = cadd(E0, O0); d[4] = csub(E0, O0);
    d[1] = cadd(E1, T1); d[5] = csub(E1, T1);
    d[2] = cadd(E2, T2); d[6] = csub(E2, T2);
    d[3] = cadd(E3, T3); d[7] = csub(E3, T3);
}

// in-place DFT-16 on v[0..15] (v = time samples, overwritten with spectrum)
__device__ __forceinline__ void dft16_ip(float2* v) {
    float2 e[8], o[8];
#pragma unroll
    for (int r = 0; r < 8; r++) { e[r] = v[2 * r]; o[r] = v[2 * r + 1]; }
    float2 E[8], O[8];
    radix8(e, E);
    radix8(o, O);
    const float C1 = 0.92387953251128674f, S1 = 0.38268343236508978f;
    const float R2 = 0.70710678118654752f;
    float2 T[8];
    T[0] = O[0];
    T[1] = mulW(O[1], C1, S1);
    T[2] = mulW(O[2], R2, R2);
    T[3] = mulW(O[3], S1, C1);
    T[4] = mnegi(O[4]);
    T[5] = mnegi(mulW(O[5], C1, S1));
    T[6] = mnegi(mulW(O[6], R2, R2));
    T[7] = mnegi(mulW(O[7], S1, C1));
#pragma unroll
    for (int k = 0; k < 8; k++) {
        v[k]     = cadd(E[k], T[k]);
        v[k + 8] = csub(E[k], T[k]);
    }
}

// forward 2048-pt complex FFT, in place in smem, radices 16*16*8, 128 threads.
// Stockham: stage(R,Ns): v[r]=src[j + r*N/R]; v[r]*=W_{R*Ns}^{(j%Ns)r};
//           dst[(j/Ns)*Ns*R + j%Ns + r*Ns] = DFT_R(v)[r]
__device__ __forceinline__ void fft2048_ip(float2* buf, int t) {
    // stage 1: R=16, Ns=1 (no twiddle)
    {
        float2 v[16];
#pragma unroll
        for (int r = 0; r < 16; r++) v[r] = buf[PADi(t + (r << 7))];
        dft16_ip(v);
        __syncthreads();
        int dbase = t << 4;
#pragma unroll
        for (int r = 0; r < 16; r++) buf[PADi(dbase + r)] = v[r];
    }
    __syncthreads();
    // stage 2: R=16, Ns=16
    {
        float2 v[16];
#pragma unroll
        for (int r = 0; r < 16; r++) v[r] = buf[PADi(t + (r << 7))];
        int tm = (t & 15) << 3;   // (j%16) * (2048/256)
#pragma unroll
        for (int r = 1; r < 16; r++) v[r] = cmulf(v[r], g_t2048[tm * r]);
        dft16_ip(v);
        __syncthreads();
        int dbase = ((t >> 4) << 8) + (t & 15);
#pragma unroll
        for (int r = 0; r < 16; r++) buf[PADi(dbase + (r << 4))] = v[r];
    }
    __syncthreads();
    // stage 3: R=8, Ns=256; per-thread slots are read AND written by the same
    // thread only (j ≡ t mod 128) -> in-place, no internal barrier.
#pragma unroll
    for (int h = 0; h < 2; h++) {
        int j = t + (h << 7);   // 0..255
        float2 v[8], d[8];
#pragma unroll
        for (int r = 0; r < 8; r++) v[r] = buf[PADi(j + (r << 8))];
#pragma unroll
        for (int r = 1; r < 8; r++) v[r] = cmulf(v[r], g_t2048[j * r]);
        radix8(v, d);
#pragma unroll
        for (int r = 0; r < 8; r++) buf[PADi(j + (r << 8))] = d[r];
    }
    __syncthreads();
}

// ---------------- main per-row kernel ----------------
__global__ void __launch_bounds__(NTHR, 6) fourier_rows_k() {
    __shared__ float2 buf[PADB];
    __shared__ unsigned hist[256];
    __shared__ unsigned warpsum[4];
    __shared__ unsigned scal[2];

    int t = threadIdx.x;
    float* rp = g_work + (size_t)blockIdx.x * LEN;

    // load row as packed complex z[n] = x[2n] + i x[2n+1] (2 complex per LDG.128)
    for (int i = t; i < NF / 2; i += NTHR) {
        float4 v = reinterpret_cast<const float4*>(rp)[i];
        buf[PADi(2 * i)]     = make_float2(v.x, v.y);
        buf[PADi(2 * i + 1)] = make_float2(v.z, v.w);
    }
    __syncthreads();

    fft2048_ip(buf, t);   // Z in buf

    // rfft split, in place, pairwise (k, 2048-k); one thread owns both slots.
    // X[k] = E + W_k*O ;  W_{2048-k} = (-W.x, W.y)
    for (int k = t; k <= NF / 2; k += NTHR) {
        float2 Zk = buf[PADi(k & (NF - 1))];
        float2 Zn = buf[PADi((NF - k) & (NF - 1))];
        float2 W  = g_tsplit[k];
        float2 E  = make_float2(0.5f * (Zk.x + Zn.x), 0.5f * (Zk.y - Zn.y));
        float2 D  = make_float2(Zk.x - Zn.x, Zk.y + Zn.y);
        float2 O  = make_float2(0.5f * D.y, -0.5f * D.x);   // D/(2i)
        float2 Xk = cadd(E, cmulf(O, W));
        float2 E2 = make_float2(0.5f * (Zn.x + Zk.x), 0.5f * (Zn.y - Zk.y));
        float2 D2 = make_float2(Zn.x - Zk.x, Zn.y + Zk.y);
        float2 O2 = make_float2(0.5f * D2.y, -0.5f * D2.x);
        float2 W2 = make_float2(-W.x, W.y);
        float2 Xn = cadd(E2, cmulf(O2, W2));
        buf[PADi(k)] = Xk;
        buf[PADi(NF - k)] = Xn;     // k=0 -> Nyquist slot PADi(2048)
    }
    __syncthreads();

    // keys = bits(|X|^2), thread t owns bins t*VPT .. t*VPT+VPT-1
    unsigned keys[VPT];
#pragma unroll
    for (int v = 0; v < VPT; v++) {
        int k = t * VPT + v;
        if (k <= NF) {
            float2 X = buf[PADi(k)];
            keys[v] = __float_as_uint(X.x * X.x + X.y * X.y);
        } else {
            keys[v] = 0u;
        }
    }

    // radix-select the TOPK-th largest key: 4 passes of 8 bits, MSB first
    unsigned pref = 0u;
    int remain = TOPK;
#pragma unroll
    for (int shift = 24; shift >= 0; shift -= 8) {
        hist[t] = 0u;
        hist[t + 128] = 0u;
        __syncthreads();
        unsigned himask = (shift == 24) ? 0u : (0xFFFFFFFFu << (shift + 8));
#pragma unroll
        for (int v = 0; v < VPT; v++) {
            unsigned key = keys[v];
            unsigned bucket = ((key & himask) == (pref & himask))
                                  ? ((key >> shift) & 255u) : 0xFFFFu;
            unsigned mm = __match_any_sync(0xFFFFFFFFu, bucket);
            if (bucket != 0xFFFFu && (t & 31) == (__ffs(mm) - 1))
                atomicAdd(&hist[bucket], (unsigned)__popc(mm));
        }
        __syncthreads();
        if (t < 32) {
            unsigned cnts[8]; unsigned lsum = 0;
#pragma unroll
            for (int e = 0; e < 8; e++) { cnts[e] = hist[255 - (t * 8 + e)]; lsum += cnts[e]; }
            unsigned inc = lsum;
#pragma unroll
            for (int o = 1; o < 32; o <<= 1) {
                unsigned nn = __shfl_up_sync(0xFFFFFFFFu, inc, o);
                if (t >= o) inc += nn;
            }
            int excl = (int)(inc - lsum);  // keys strictly above this lane's range
            if (excl < remain && remain <= (int)inc) {
                int run = excl;
#pragma unroll
                for (int e = 0; e < 8; e++) {
                    if (run < remain && remain <= run + (int)cnts[e]) {
                        scal[0] = (unsigned)(255 - (t * 8 + e));
                        scal[1] = (unsigned)run;
                    }
                    run += (int)cnts[e];
                }
            }
        }
        __syncthreads();
        pref |= (scal[0] << shift);
        remain -= (int)scal[1];
        __syncthreads();
    }
    unsigned Tkey = pref;   // exact key of the TOPK-th largest
    int extra = remain;     // ties (== Tkey) to keep, lowest bin index first

    // per-thread exclusive rank among ties (global order = bin index order)
    int local = 0;
#pragma unroll
    for (int v = 0; v < VPT; v++) {
        int k = t * VPT + v;
        if (k <= NF && keys[v] == Tkey) local++;
    }
    int inc2 = local;
#pragma unroll
    for (int o = 1; o < 32; o <<= 1) {
        int nn = __shfl_up_sync(0xFFFFFFFFu, inc2, o);
        if ((t & 31) >= o) inc2 += nn;
    }
    if ((t & 31) == 31) warpsum[t >> 5] = (unsigned)inc2;
    __syncthreads();
    if (t == 0) {
        unsigned acc = 0;
        for (int w = 0; w < 4; w++) { unsigned s = warpsum[w]; warpsum[w] = acc; acc += s; }
    }
    __syncthreads();
    int rank = (int)warpsum[t >> 5] + (inc2 - local);

    // zero non-selected bins of X (in place)
#pragma unroll
    for (int v = 0; v < VPT; v++) {
        int k = t * VPT + v;
        if (k <= NF) {
            bool sel;
            if (keys[v] > Tkey) sel = true;
            else if (keys[v] == Tkey) { sel = (rank < extra); rank++; }
            else sel = false;
            if (!sel) buf[PADi(k)] = make_float2(0.f, 0.f);
        }
    }
    __syncthreads();

    // rebuild conj(Z') from masked X, in place, pairwise.
    for (int k = t; k <= NF / 2; k += NTHR) {
        float2 Xk = buf[PADi(k)];
        float2 Xn = buf[PADi(NF - k)];   // k=0 -> Nyquist slot
        float2 W  = g_tsplit[k];
        float2 E  = make_float2(0.5f * (Xk.x + Xn.x), 0.5f * (Xk.y - Xn.y));
        float2 Dh = make_float2(0.5f * (Xk.x - Xn.x), 0.5f * (Xk.y + Xn.y)); // W^k O
        float2 O  = cmulf(Dh, make_float2(W.x, -W.y));
        float2 zck = make_float2(E.x - O.y, -(E.y + O.x));   // conj(Z'[k])
        float2 E2  = make_float2(0.5f * (Xn.x + Xk.x), 0.5f * (Xn.y - Xk.y));
        float2 Dh2 = make_float2(0.5f * (Xn.x - Xk.x), 0.5f * (Xn.y + Xk.y));
        float2 O2  = cmulf(Dh2, make_float2(-W.x, -W.y));
        float2 zcn = make_float2(E2.x - O2.y, -(E2.y + O2.x));
        buf[PADi(k)] = zck;
        if (k > 0) buf[PADi(NF - k)] = zcn;   // slot 2048 not part of Z'
    }
    __syncthreads();

    fft2048_ip(buf, t);       // F = FFT(conj(Z')) = NF * conj(z')

    const float invn = 1.0f / (float)NF;
    for (int i = t; i < NF / 2; i += NTHR) {
        float2 a = buf[PADi(2 * i)];
        float2 b = buf[PADi(2 * i + 1)];
        // z'[n] = conj(F[n])/NF : x'[2n] = F.x/NF, x'[2n+1] = -F.y/NF
        float4 v = make_float4(a.x * invn, -a.y * invn, b.x * invn, -b.y * invn);
        reinterpret_cast<float4*>(rp)[i] = v;
    }
}

// ---------------- launch ----------------
extern "C" void kernel_launch(void* const* d_in, const int* in_sizes, int n_in,
                              void* d_out, int out_size) {
    const float* x = (const float*)d_in[0];
    float* out = (float*)d_out;

    init_twiddles_k<<<(NF + 255) / 256, 256>>>();

    dim3 tb(8, 32);
    dim3 tg(LEN / 32, CH / 32, NB);
    transpose_in_k<<<tg, tb>>>(x);

    fourier_rows_k<<<NB * CH, NTHR>>>();

    transpose_out_k<<<tg, tb>>>(out);
}

// round 5
// speedup vs baseline: 1.5223x; 1.1168x over previous
#include <cuda_runtime.h>
#include <math.h>

#define NB    32
#define LEN   4096
#define CH    128
#define NF    2048      // packed complex FFT size (LEN/2)
#define TOPK  64
#define NTHR  128
#define VPT   17        // 128*17 = 2176 >= 2049 bins
#define PADB  2180      // PADi(2048)=2176 is the Nyquist slot

// ---------------- device globals (scratch; no runtime allocation) ----------------
__device__ float  g_work[(size_t)NB * CH * LEN];   // 64 MB, (B,C,L)
__device__ float2 g_t2048[NF];                     // e^{-2pi i t / 2048}
__device__ float2 g_tsplit[NF];                    // e^{-pi i k / 2048}

// ---------------- twiddle init ----------------
__global__ void init_twiddles_k() {
    int i = blockIdx.x * blockDim.x + threadIdx.x;
    if (i < NF) {
        const double PI = 3.14159265358979323846;
        double a = -2.0 * PI * (double)i / (double)NF;
        g_t2048[i] = make_float2((float)cos(a), (float)sin(a));
        double b = -PI * (double)i / (double)NF;
        g_tsplit[i] = make_float2((float)cos(b), (float)sin(b));
    }
}

// ---------------- transposes (float4 vectorized, blockDim (8,32)) ----------------
__global__ void transpose_in_k(const float* __restrict__ in) {
    __shared__ float tile[32][33];
    int b = blockIdx.z;
    int l0 = blockIdx.x << 5, c0 = blockIdx.y << 5;
    int x = threadIdx.x, y = threadIdx.y;
    float4 v = *reinterpret_cast<const float4*>(
        in + (size_t)b * LEN * CH + (size_t)(l0 + y) * CH + c0 + 4 * x);
    tile[y][4 * x + 0] = v.x; tile[y][4 * x + 1] = v.y;
    tile[y][4 * x + 2] = v.z; tile[y][4 * x + 3] = v.w;
    __syncthreads();
    float4 w;
    w.x = tile[4 * x + 0][y]; w.y = tile[4 * x + 1][y];
    w.z = tile[4 * x + 2][y]; w.w = tile[4 * x + 3][y];
    *reinterpret_cast<float4*>(
        g_work + (size_t)b * CH * LEN + (size_t)(c0 + y) * LEN + l0 + 4 * x) = w;
}

__global__ void transpose_out_k(float* __restrict__ out) {
    __shared__ float tile[32][33];
    int b = blockIdx.z;
    int l0 = blockIdx.x << 5, c0 = blockIdx.y << 5;
    int x = threadIdx.x, y = threadIdx.y;
    float4 v = *reinterpret_cast<const float4*>(
        g_work + (size_t)b * CH * LEN + (size_t)(c0 + y) * LEN + l0 + 4 * x);
    tile[4 * x + 0][y] = v.x; tile[4 * x + 1][y] = v.y;
    tile[4 * x + 2][y] = v.z; tile[4 * x + 3][y] = v.w;
    __syncthreads();
    float4 w;
    w.x = tile[y][4 * x + 0]; w.y = tile[y][4 * x + 1];
    w.z = tile[y][4 * x + 2]; w.w = tile[y][4 * x + 3];
    *reinterpret_cast<float4*>(
        out + (size_t)b * LEN * CH + (size_t)(l0 + y) * CH + c0 + 4 * x) = w;
}

// ---------------- complex helpers ----------------
__device__ __forceinline__ int PADi(int i) { return i + (i >> 4); }
__device__ __forceinline__ float2 cadd(float2 a, float2 b) { return make_float2(a.x + b.x, a.y + b.y); }
__device__ __forceinline__ float2 csub(float2 a, float2 b) { return make_float2(a.x - b.x, a.y - b.y); }
__device__ __forceinline__ float2 cmulf(float2 a, float2 b) {
    return make_float2(a.x * b.x - a.y * b.y, a.x * b.y + a.y * b.x);
}
__device__ __forceinline__ float2 mnegi(float2 a) { return make_float2(a.y, -a.x); } // a * (-i)
// a * (c - i s)
__device__ __forceinline__ float2 mulW(float2 a, float c, float s) {
    return make_float2(a.x * c + a.y * s, a.y * c - a.x * s);
}

__device__ __forceinline__ void radix8(const float2* c, float2* d) {
    float2 s0 = cadd(c[0], c[4]), s1 = csub(c[0], c[4]);
    float2 s2 = cadd(c[2], c[6]), s3 = mnegi(csub(c[2], c[6]));
    float2 E0 = cadd(s0, s2), E2 = csub(s0, s2);
    float2 E1 = cadd(s1, s3), E3 = csub(s1, s3);
    float2 u0 = cadd(c[1], c[5]), u1 = csub(c[1], c[5]);
    float2 u2 = cadd(c[3], c[7]), u3 = mnegi(csub(c[3], c[7]));
    float2 O0 = cadd(u0, u2), O2 = csub(u0, u2);
    float2 O1 = cadd(u1, u3), O3 = csub(u1, u3);
    const float r2 = 0.70710678118654752f;
    float2 T1 = make_float2(r2 * (O1.x + O1.y), r2 * (O1.y - O1.x));   // W8^1*O1
    float2 T2 = mnegi(O2);                                             // W8^2*O2
    float2 T3 = make_float2(r2 * (O3.y - O3.x), r2 * (-O3.x - O3.y));  // W8^3*O3
    d[0] = cadd(E0, O0); d[4] = csub(E0, O0);
    d[1] = cadd(E1, T1); d[5] = csub(E1, T1);
    d[2] = cadd(E2, T2); d[6] = csub(E2, T2);
    d[3] = cadd(E3, T3); d[7] = csub(E3, T3);
}

// in-place DFT-16 on v[0..15] (v = time samples, overwritten with spectrum)
__device__ __forceinline__ void dft16_ip(float2* v) {
    float2 e[8], o[8];
#pragma unroll
    for (int r = 0; r < 8; r++) { e[r] = v[2 * r]; o[r] = v[2 * r + 1]; }
    float2 E[8], O[8];
    radix8(e, E);
    radix8(o, O);
    const float C1 = 0.92387953251128674f, S1 = 0.38268343236508978f;
    const float R2 = 0.70710678118654752f;
    float2 T[8];
    T[0] = O[0];
    T[1] = mulW(O[1], C1, S1);
    T[2] = mulW(O[2], R2, R2);
    T[3] = mulW(O[3], S1, C1);
    T[4] = mnegi(O[4]);
    T[5] = mnegi(mulW(O[5], C1, S1));
    T[6] = mnegi(mulW(O[6], R2, R2));
    T[7] = mnegi(mulW(O[7], S1, C1));
#pragma unroll
    for (int k = 0; k < 8; k++) {
        v[k]     = cadd(E[k], T[k]);
        v[k + 8] = csub(E[k], T[k]);
    }
}

// forward 2048-pt complex FFT, in place in smem, radices 16*16*8, 128 threads.
__device__ __forceinline__ void fft2048_ip(float2* buf, int t) {
    // stage 1: R=16, Ns=1 (no twiddle); writes lane-stride 16 -> slot t mod 16: conflict-free
    {
        float2 v[16];
#pragma unroll
        for (int r = 0; r < 16; r++) v[r] = buf[PADi(t + (r << 7))];
        dft16_ip(v);
        __syncthreads();
        int dbase = t << 4;
#pragma unroll
        for (int r = 0; r < 16; r++) buf[PADi(dbase + r)] = v[r];
    }
    __syncthreads();
    // stage 2: R=16, Ns=16; writes slot (j&15 + r) mod 16: conflict-free
    {
        float2 v[16];
#pragma unroll
        for (int r = 0; r < 16; r++) v[r] = buf[PADi(t + (r << 7))];
        int tm = (t & 15) << 3;   // (j%16) * (2048/256)
#pragma unroll
        for (int r = 1; r < 16; r++) v[r] = cmulf(v[r], g_t2048[tm * r]);
        dft16_ip(v);
        __syncthreads();
        int dbase = ((t >> 4) << 8) + (t & 15);
#pragma unroll
        for (int r = 0; r < 16; r++) buf[PADi(dbase + (r << 4))] = v[r];
    }
    __syncthreads();
    // stage 3: R=8, Ns=256; same-thread slots -> in-place, no internal barrier
#pragma unroll
    for (int h = 0; h < 2; h++) {
        int j = t + (h << 7);   // 0..255
        float2 v[8], d[8];
#pragma unroll
        for (int r = 0; r < 8; r++) v[r] = buf[PADi(j + (r << 8))];
#pragma unroll
        for (int r = 1; r < 8; r++) v[r] = cmulf(v[r], g_t2048[j * r]);
        radix8(v, d);
#pragma unroll
        for (int r = 0; r < 8; r++) buf[PADi(j + (r << 8))] = d[r];
    }
    __syncthreads();
}

// ---------------- main per-row kernel ----------------
__global__ void __launch_bounds__(NTHR, 6) fourier_rows_k() {
    __shared__ float2 buf[PADB];
    __shared__ unsigned hist[256];
    __shared__ unsigned warpsum[4];
    __shared__ unsigned scal[2];

    int t = threadIdx.x;
    float* rp = g_work + (size_t)blockIdx.x * LEN;

    // load row as packed complex z[n] = x[2n] + i x[2n+1] (2 complex per LDG.128)
    for (int i = t; i < NF / 2; i += NTHR) {
        float4 v = reinterpret_cast<const float4*>(rp)[i];
        buf[PADi(2 * i)]     = make_float2(v.x, v.y);
        buf[PADi(2 * i + 1)] = make_float2(v.z, v.w);
    }
    __syncthreads();

    fft2048_ip(buf, t);   // Z in buf

    // rfft split, in place, pairwise (k, 2048-k); one thread owns both slots.
    for (int k = t; k <= NF / 2; k += NTHR) {
        float2 Zk = buf[PADi(k & (NF - 1))];
        float2 Zn = buf[PADi((NF - k) & (NF - 1))];
        float2 W  = g_tsplit[k];
        float2 E  = make_float2(0.5f * (Zk.x + Zn.x), 0.5f * (Zk.y - Zn.y));
        float2 D  = make_float2(Zk.x - Zn.x, Zk.y + Zn.y);
        float2 O  = make_float2(0.5f * D.y, -0.5f * D.x);   // D/(2i)
        float2 Xk = cadd(E, cmulf(O, W));
        float2 E2 = make_float2(0.5f * (Zn.x + Zk.x), 0.5f * (Zn.y - Zk.y));
        float2 D2 = make_float2(Zn.x - Zk.x, Zn.y + Zk.y);
        float2 O2 = make_float2(0.5f * D2.y, -0.5f * D2.x);
        float2 W2 = make_float2(-W.x, W.y);
        float2 Xn = cadd(E2, cmulf(O2, W2));
        buf[PADi(k)] = Xk;
        buf[PADi(NF - k)] = Xn;     // k=0 -> Nyquist slot PADi(2048)
    }
    __syncthreads();

    // keys = bits(|X|^2), thread t owns bins t*VPT .. t*VPT+VPT-1
    unsigned keys[VPT];
#pragma unroll
    for (int v = 0; v < VPT; v++) {
        int k = t * VPT + v;
        if (k <= NF) {
            float2 X = buf[PADi(k)];
            keys[v] = __float_as_uint(X.x * X.x + X.y * X.y);
        } else {
            keys[v] = 0u;
        }
    }

    // radix-select the TOPK-th largest key: 4 passes of 8 bits, MSB first
    unsigned pref = 0u;
    int remain = TOPK;
#pragma unroll
    for (int shift = 24; shift >= 0; shift -= 8) {
        hist[t] = 0u;
        hist[t + 128] = 0u;
        __syncthreads();
        unsigned himask = (shift == 24) ? 0u : (0xFFFFFFFFu << (shift + 8));
#pragma unroll
        for (int v = 0; v < VPT; v++) {
            unsigned key = keys[v];
            unsigned bucket = ((key & himask) == (pref & himask))
                                  ? ((key >> shift) & 255u) : 0xFFFFu;
            unsigned mm = __match_any_sync(0xFFFFFFFFu, bucket);
            if (bucket != 0xFFFFu && (t & 31) == (__ffs(mm) - 1))
                atomicAdd(&hist[bucket], (unsigned)__popc(mm));
        }
        __syncthreads();
        if (t < 32) {
            unsigned cnts[8]; unsigned lsum = 0;
#pragma unroll
            for (int e = 0; e < 8; e++) { cnts[e] = hist[255 - (t * 8 + e)]; lsum += cnts[e]; }
            unsigned inc = lsum;
#pragma unroll
            for (int o = 1; o < 32; o <<= 1) {
                unsigned nn = __shfl_up_sync(0xFFFFFFFFu, inc, o);
                if (t >= o) inc += nn;
            }
            int excl = (int)(inc - lsum);  // keys strictly above this lane's range
            if (excl < remain && remain <= (int)inc) {
                int run = excl;
#pragma unroll
                for (int e = 0; e < 8; e++) {
                    if (run < remain && remain <= run + (int)cnts[e]) {
                        scal[0] = (unsigned)(255 - (t * 8 + e));
                        scal[1] = (unsigned)run;
                    }
                    run += (int)cnts[e];
                }
            }
        }
        __syncthreads();
        pref |= (scal[0] << shift);
        remain -= (int)scal[1];
        __syncthreads();
    }
    unsigned Tkey = pref;   // exact key of the TOPK-th largest
    int extra = remain;     // ties (== Tkey) to keep, lowest bin index first

    // per-thread exclusive rank among ties (global order = bin index order)
    int local = 0;
#pragma unroll
    for (int v = 0; v < VPT; v++) {
        int k = t * VPT + v;
        if (k <= NF && keys[v] == Tkey) local++;
    }
    int inc2 = local;
#pragma unroll
    for (int o = 1; o < 32; o <<= 1) {
        int nn = __shfl_up_sync(0xFFFFFFFFu, inc2, o);
        if ((t & 31) >= o) inc2 += nn;
    }
    if ((t & 31) == 31) warpsum[t >> 5] = (unsigned)inc2;
    __syncthreads();
    if (t == 0) {
        unsigned acc = 0;
        for (int w = 0; w < 4; w++) { unsigned s = warpsum[w]; warpsum[w] = acc; acc += s; }
    }
    __syncthreads();
    int rank = (int)warpsum[t >> 5] + (inc2 - local);

    // zero non-selected bins of X (in place)
#pragma unroll
    for (int v = 0; v < VPT; v++) {
        int k = t * VPT + v;
        if (k <= NF) {
            bool sel;
            if (keys[v] > Tkey) sel = true;
            else if (keys[v] == Tkey) { sel = (rank < extra); rank++; }
            else sel = false;
            if (!sel) buf[PADi(k)] = make_float2(0.f, 0.f);
        }
    }
    __syncthreads();

    // rebuild conj(Z') from masked X, in place, pairwise.
    for (int k = t; k <= NF / 2; k += NTHR) {
        float2 Xk = buf[PADi(k)];
        float2 Xn = buf[PADi(NF - k)];   // k=0 -> Nyquist slot
        float2 W  = g_tsplit[k];
        float2 E  = make_float2(0.5f * (Xk.x + Xn.x), 0.5f * (Xk.y - Xn.y));
        float2 Dh = make_float2(0.5f * (Xk.x - Xn.x), 0.5f * (Xk.y + Xn.y)); // W^k O
        float2 O  = cmulf(Dh, make_float2(W.x, -W.y));
        float2 zck = make_float2(E.x - O.y, -(E.y + O.x));   // conj(Z'[k])
        float2 E2  = make_float2(0.5f * (Xn.x + Xk.x), 0.5f * (Xn.y - Xk.y));
        float2 Dh2 = make_float2(0.5f * (Xn.x - Xk.x), 0.5f * (Xn.y + Xk.y));
        float2 O2  = cmulf(Dh2, make_float2(-W.x, -W.y));
        float2 zcn = make_float2(E2.x - O2.y, -(E2.y + O2.x));
        buf[PADi(k)] = zck;
        if (k > 0) buf[PADi(NF - k)] = zcn;   // slot 2048 not part of Z'
    }
    __syncthreads();

    fft2048_ip(buf, t);       // F = FFT(conj(Z')) = NF * conj(z')

    const float invn = 1.0f / (float)NF;
    for (int i = t; i < NF / 2; i += NTHR) {
        float2 a = buf[PADi(2 * i)];
        float2 b = buf[PADi(2 * i + 1)];
        // z'[n] = conj(F[n])/NF : x'[2n] = F.x/NF, x'[2n+1] = -F.y/NF
        float4 v = make_float4(a.x * invn, -a.y * invn, b.x * invn, -b.y * invn);
        reinterpret_cast<float4*>(rp)[i] = v;
    }
}

// ---------------- launch ----------------
extern "C" void kernel_launch(void* const* d_in, const int* in_sizes, int n_in,
                              void* d_out, int out_size) {
    const float* x = (const float*)d_in[0];
    float* out = (float*)d_out;

    init_twiddles_k<<<(NF + 255) / 256, 256>>>();

    dim3 tb(8, 32);
    dim3 tg(LEN / 32, CH / 32, NB);
    transpose_in_k<<<tg, tb>>>(x);

    fourier_rows_k<<<NB * CH, NTHR>>>();

    transpose_out_k<<<tg, tb>>>(out);
}